// round 14
// baseline (speedup 1.0000x reference)
#include <cuda_runtime.h>

#define TB 4
#define TSEQ 8192
#define NR 64
#define N2R 128
#define NS 256
#define NL 16
#define SQRT_HALF 0.70710678118654752f
#define FRAG64 524288   // words per [64k x TSEQ] fragment plane (512 tiles * 1024)

__device__ float g_x[2][TB][NR][TSEQ];
__device__ unsigned g_actsF[NL * TB * 2 * FRAG64];   // [l][b][hi|lo]
__device__ unsigned g_h1F[TB * 2 * 4 * FRAG64];      // [b][hi|lo][kchunk]
__device__ unsigned g_h2F[TB * 2 * 4 * FRAG64];
__device__ unsigned g_wdil[NL * 2 * 2 * 8192];       // [l][tap][hi|lo]
__device__ unsigned g_wres[NL * 2 * 4096];
__device__ unsigned g_wskip[NL * 2 * 16384];
__device__ unsigned g_wcond[2 * 2 * 131072];         // [kchunk][hi|lo]
__device__ unsigned g_wout[4 * 2 * 16384];
__device__ unsigned g_wend[4 * 2 * 16384];

__device__ __forceinline__ unsigned tf32r(float v) {
    unsigned u; asm("cvt.rna.tf32.f32 %0,%1;" : "=r"(u) : "f"(v)); return u;
}
__device__ __forceinline__ void mma8(float* d, uint4 a, uint2 b) {
    asm volatile(
        "mma.sync.aligned.m16n8k8.row.col.f32.tf32.tf32.f32 "
        "{%0,%1,%2,%3},{%4,%5,%6,%7},{%8,%9},{%0,%1,%2,%3};"
        : "+f"(d[0]), "+f"(d[1]), "+f"(d[2]), "+f"(d[3])
        : "r"(a.x), "r"(a.y), "r"(a.z), "r"(a.w), "r"(b.x), "r"(b.y));
}
// A-fragment slot for (time t [abs or tile-rel], k<64)
__device__ __forceinline__ int afrag_abs(int t, int k) {
    return (((t >> 4) * 8 + (k >> 3)) * 32 + (((t & 7) << 2) | (k & 3))) * 4
           + (((t >> 3) & 1) | (((k >> 2) & 1) << 1));
}
// B-fragment slot for (out-channel o, k<64)
__device__ __forceinline__ int bfrag(int o, int k) {
    return (((o >> 3) * 8 + (k >> 3)) * 32 + (((o & 7) << 2) | (k & 3))) * 2 + ((k >> 2) & 1);
}
__device__ __forceinline__ void storeF(unsigned* hb, unsigned* lb, int t, int k, float v) {
    unsigned h = tf32r(v);
    int idx = afrag_abs(t, k);
    hb[idx] = h; lb[idx] = tf32r(v - __uint_as_float(h));
}

// D[NT][4] += A(64k) x B, 3-mma tf32x2. A: [tile][kc][128] planes; B: global frags.
template<int NT>
__device__ __forceinline__ void mma_AB(float (*D)[4], const unsigned* Ah, const unsigned* Al,
                                       const unsigned* __restrict__ W, int wsz,
                                       int tt, int obase, int lane) {
#pragma unroll
    for (int kc = 0; kc < 8; ++kc) {
        uint4 ah = *(const uint4*)&Ah[(tt * 8 + kc) * 128 + lane * 4];
        uint4 al = *(const uint4*)&Al[(tt * 8 + kc) * 128 + lane * 4];
#pragma unroll
        for (int nt = 0; nt < NT; ++nt) {
            int wb = ((obase + nt) * 8 + kc) * 64 + lane * 2;
            uint2 bh = *(const uint2*)&W[wb];
            uint2 bl = *(const uint2*)&W[wsz + wb];
            mma8(D[nt], ah, bh);
            mma8(D[nt], al, bh);
            mma8(D[nt], ah, bl);
        }
    }
}

// stage A tile [64k x TT t] (hi at AF, lo at AF+64*TT), zero-pad t<0
template<int NTHR, int TT>
__device__ __forceinline__ void stageA(unsigned* AF, const float* __restrict__ src,
                                       int t0, int tid) {
    for (int i = tid; i < 64 * TT; i += NTHR) {
        int k = i / TT, tl = i % TT, tg = t0 + tl;
        float v = (tg >= 0) ? src[(size_t)k * TSEQ + tg] : 0.f;
        unsigned h = tf32r(v);
        int off = afrag_abs(tl, k);
        AF[off] = h; AF[64 * TT + off] = tf32r(v - __uint_as_float(h));
    }
}

// ---------------------------------------------------------------------------
// Convert all weights to fragment hi/lo planes in global (one pass).
// ---------------------------------------------------------------------------
__global__ void wprep(const float* __restrict__ dW, const float* __restrict__ rW,
                      const float* __restrict__ sW, const float* __restrict__ cW,
                      const float* __restrict__ oW, const float* __restrict__ eW) {
    int idx = blockIdx.x * 256 + threadIdx.x;
    if (idx < 262144) {                       // dilate: 32 matrices [128x64]
        int m = idx >> 13, rem = idx & 8191, o = rem >> 6, k = rem & 63;
        int l = m >> 1, tap = m & 1;
        float v = dW[(size_t)l * 16384 + o * 128 + k * 2 + tap];
        unsigned h = tf32r(v); unsigned* d = g_wdil + (size_t)m * 16384;
        int f = bfrag(o, k); d[f] = h; d[8192 + f] = tf32r(v - __uint_as_float(h));
        return;
    }
    idx -= 262144;
    if (idx < 61440) {                        // res: 15 matrices [64x64]
        int m = idx >> 12, rem = idx & 4095, o = rem >> 6, k = rem & 63;
        float v = rW[(size_t)m * 4096 + o * 64 + k];
        unsigned h = tf32r(v); unsigned* d = g_wres + (size_t)m * 8192;
        int f = bfrag(o, k); d[f] = h; d[4096 + f] = tf32r(v - __uint_as_float(h));
        return;
    }
    idx -= 61440;
    if (idx < 262144) {                       // skip: 16 matrices [256x64]
        int m = idx >> 14, rem = idx & 16383, o = rem >> 6, k = rem & 63;
        float v = sW[(size_t)m * 16384 + o * 64 + k];
        unsigned h = tf32r(v); unsigned* d = g_wskip + (size_t)m * 32768;
        int f = bfrag(o, k); d[f] = h; d[16384 + f] = tf32r(v - __uint_as_float(h));
        return;
    }
    idx -= 262144;
    if (idx < 262144) {                       // cond: 2 kchunks [2048x64]
        int m = idx >> 17, rem = idx & 131071, o = rem >> 6, k = rem & 63;
        float v = cW[(size_t)o * 128 + m * 64 + k];
        unsigned h = tf32r(v); unsigned* d = g_wcond + (size_t)m * 262144;
        int f = bfrag(o, k); d[f] = h; d[131072 + f] = tf32r(v - __uint_as_float(h));
        return;
    }
    idx -= 262144;
    if (idx < 65536) {                        // conv_out: 4 kchunks [256x64]
        int m = idx >> 14, rem = idx & 16383, o = rem >> 6, k = rem & 63;
        float v = oW[(size_t)o * 256 + m * 64 + k];
        unsigned h = tf32r(v); unsigned* d = g_wout + (size_t)m * 32768;
        int f = bfrag(o, k); d[f] = h; d[16384 + f] = tf32r(v - __uint_as_float(h));
        return;
    }
    idx -= 65536;
    if (idx < 65536) {                        // conv_end
        int m = idx >> 14, rem = idx & 16383, o = rem >> 6, k = rem & 63;
        float v = eW[(size_t)o * 256 + m * 64 + k];
        unsigned h = tf32r(v); unsigned* d = g_wend + (size_t)m * 32768;
        int f = bfrag(o, k); d[f] = h; d[16384 + f] = tf32r(v - __uint_as_float(h));
    }
}

// ---------------------------------------------------------------------------
__global__ void embed_kernel(const int* __restrict__ tokens,
                             const float* __restrict__ embed) {
    int t = blockIdx.x * blockDim.x + threadIdx.x;
    int b = blockIdx.y;
    const float* e = embed + tokens[b * TSEQ + t] * NR;
#pragma unroll 8
    for (int r = 0; r < NR; ++r) g_x[0][b][r][t] = e[r];
}

// ---------------------------------------------------------------------------
__global__ void __launch_bounds__(512)
cond_kernel(const float* __restrict__ features, const float* __restrict__ cond_b,
            float* __restrict__ cond_out) {
    extern __shared__ unsigned smu[];
    unsigned* AF = smu;                       // 16384 words
    float* sB = (float*)(smu + 16384);
    int tid = threadIdx.x, lane = tid & 31, warp = tid >> 5, tt = warp & 7, oh = warp >> 3;
    int t0 = blockIdx.x * 128, ob = blockIdx.y * 128, b = blockIdx.z;
    if (tid < 128) sB[tid] = cond_b[ob + tid];
    float D[8][4] = {};
    for (int ch = 0; ch < 2; ++ch) {
        __syncthreads();
        stageA<512, 128>(AF, features + ((size_t)b * 128 + ch * 64) * TSEQ, t0, tid);
        __syncthreads();
        mma_AB<8>(D, AF, AF + 8192, g_wcond + ch * 262144, 131072, tt, (ob >> 3) + oh * 8, lane);
    }
    int g = lane >> 2, tg = lane & 3, t1 = t0 + tt * 16 + g;
#pragma unroll
    for (int nt = 0; nt < 8; ++nt) {
        int o = oh * 64 + nt * 8 + tg * 2;
        size_t r0 = ((size_t)b * 2048 + ob + o) * TSEQ + t1, r1 = r0 + TSEQ;
        cond_out[r0] = D[nt][0] + sB[o];     cond_out[r1] = D[nt][1] + sB[o + 1];
        cond_out[r0 + 8] = D[nt][2] + sB[o]; cond_out[r1 + 8] = D[nt][3] + sB[o + 1];
    }
}

// ---------------------------------------------------------------------------
// Layer: TT=64, 256 threads, ~66KB smem -> 3 CTAs/SM, grid (128,4).
// ---------------------------------------------------------------------------
__global__ void __launch_bounds__(256)
layer_kernel(const float* __restrict__ dilate_b, const float* __restrict__ res_b,
             const float* __restrict__ cond_base, float* __restrict__ ia_base,
             int l, int d, int par) {
    extern __shared__ unsigned smu[];
    unsigned* XcF = smu;                 // 8192 words (hi 4096 | lo 4096)
    unsigned* XpF = smu + 8192;          // 8192
    float* sAfull = (float*)smu;         // overlays XcF after GEMM1 (128x64 f32)
    unsigned* ActsF = smu + 8192;        // overlays XpF (hi 4096 | lo 4096)
    float* sDilB = (float*)(smu + 16384);
    float* sResB = sDilB + 128;

    int tid = threadIdx.x, lane = tid & 31, warp = tid >> 5, tt = warp & 3, oh = warp >> 2;
    int t0 = blockIdx.x * 64, b = blockIdx.y;
    const float* xin = &g_x[par][b][0][0];
    float* xout = &g_x[par ^ 1][b][0][0];

    stageA<256, 64>(XcF, xin, t0, tid);
    stageA<256, 64>(XpF, xin, t0 - d, tid);
    if (tid < 128) sDilB[tid] = dilate_b[l * N2R + tid];
    if (l < NL - 1 && tid < 64) sResB[tid] = res_b[l * 64 + tid];
    __syncthreads();

    float D[8][4] = {};
    mma_AB<8>(D, XcF, XcF + 4096, g_wdil + (l * 2 + 1) * 16384, 8192, tt, oh * 8, lane);
    mma_AB<8>(D, XpF, XpF + 4096, g_wdil + (l * 2 + 0) * 16384, 8192, tt, oh * 8, lane);
    __syncthreads();

    // epilogue 1: ia = D + bias -> out; a = ia + cond -> sAfull
    int g = lane >> 2, tg = lane & 3, tl1 = tt * 16 + g, t1 = t0 + tl1;
    size_t iab = ((size_t)(b * NL + l) * N2R) * TSEQ;
#pragma unroll
    for (int nt = 0; nt < 8; ++nt) {
        int o = oh * 64 + nt * 8 + tg * 2;
        size_t r0 = iab + (size_t)o * TSEQ + t1, r1 = r0 + TSEQ;
        float i00 = D[nt][0] + sDilB[o], i01 = D[nt][1] + sDilB[o + 1];
        float i10 = D[nt][2] + sDilB[o], i11 = D[nt][3] + sDilB[o + 1];
        ia_base[r0] = i00;     ia_base[r1] = i01;
        ia_base[r0 + 8] = i10; ia_base[r1 + 8] = i11;
        sAfull[o * 64 + tl1]           = i00 + cond_base[r0];
        sAfull[(o + 1) * 64 + tl1]     = i01 + cond_base[r1];
        sAfull[o * 64 + tl1 + 8]       = i10 + cond_base[r0 + 8];
        sAfull[(o + 1) * 64 + tl1 + 8] = i11 + cond_base[r1 + 8];
    }
    __syncthreads();

    // gate -> acts fragments (global for skip, smem for res)
    unsigned* aFh = g_actsF + ((size_t)(l * TB + b)) * 2 * FRAG64;
    unsigned* aFl = aFh + FRAG64;
    for (int i = tid; i < 4096; i += 256) {
        int r = i >> 6, tl = i & 63;
        float a1 = sAfull[r * 64 + tl], a2 = sAfull[(r + 64) * 64 + tl];
        float act = tanhf(a1) * (0.5f * tanhf(0.5f * a2) + 0.5f);
        unsigned h = tf32r(act), lo = tf32r(act - __uint_as_float(h));
        int gi = afrag_abs(t0 + tl, r);
        aFh[gi] = h; aFl[gi] = lo;
        int si = afrag_abs(tl, r);
        ActsF[si] = h; ActsF[4096 + si] = lo;
    }
    __syncthreads();

    if (l < NL - 1) {
        float D3[4][4] = {};
        mma_AB<4>(D3, ActsF, ActsF + 4096, g_wres + l * 8192, 4096, tt, oh * 4, lane);
#pragma unroll
        for (int nt = 0; nt < 4; ++nt) {
            int r = oh * 32 + nt * 8 + tg * 2;
            size_t r0 = (size_t)r * TSEQ + t1, r1 = r0 + TSEQ;
            xout[r0]     = (D3[nt][0] + sResB[r]     + xin[r0])     * SQRT_HALF;
            xout[r1]     = (D3[nt][1] + sResB[r + 1] + xin[r1])     * SQRT_HALF;
            xout[r0 + 8] = (D3[nt][2] + sResB[r]     + xin[r0 + 8]) * SQRT_HALF;
            xout[r1 + 8] = (D3[nt][3] + sResB[r + 1] + xin[r1 + 8]) * SQRT_HALF;
        }
    }
}

// ---------------------------------------------------------------------------
// Skip: no staging at all; A frags from g_actsF, B frags from g_wskip.
// grid (64, 2, 4), 512 threads.
// ---------------------------------------------------------------------------
__global__ void __launch_bounds__(512)
skip_kernel(const float* __restrict__ skip_b) {
    __shared__ float sB[128];
    int tid = threadIdx.x, lane = tid & 31, warp = tid >> 5, tt = warp & 7, oh = warp >> 3;
    int t0 = blockIdx.x * 128, obh = blockIdx.y, b = blockIdx.z;
    if (tid < 128) {
        float s = 0.f;
        for (int l = 0; l < NL; ++l) s += skip_b[l * NS + obh * 128 + tid];
        sB[tid] = s;
    }
    __syncthreads();
    float D[8][4] = {};
    int tile0 = t0 >> 4;
    for (int l = 0; l < NL; ++l) {
        const unsigned* Ah = g_actsF + ((size_t)(l * TB + b)) * 2 * FRAG64 + tile0 * 1024;
        mma_AB<8>(D, Ah, Ah + FRAG64, g_wskip + l * 32768, 16384, tt, obh * 16 + oh * 8, lane);
    }
    int g = lane >> 2, tg = lane & 3, t1 = t0 + tt * 16 + g;
#pragma unroll
    for (int nt = 0; nt < 8; ++nt) {
        int o = obh * 128 + oh * 64 + nt * 8 + tg * 2;
        int ch = o >> 6, kl = o & 63, ol = o - obh * 128;
        unsigned* hb = g_h1F + (size_t)b * 8 * FRAG64 + (size_t)ch * FRAG64;
        unsigned* lb = hb + 4 * FRAG64;
        storeF(hb, lb, t1,     kl,     fmaxf(D[nt][0] + sB[ol], 0.f));
        storeF(hb, lb, t1,     kl + 1, fmaxf(D[nt][1] + sB[ol + 1], 0.f));
        storeF(hb, lb, t1 + 8, kl,     fmaxf(D[nt][2] + sB[ol], 0.f));
        storeF(hb, lb, t1 + 8, kl + 1, fmaxf(D[nt][3] + sB[ol + 1], 0.f));
    }
}

// ---------------------------------------------------------------------------
// Head convs: A frags from g_h1F/g_h2F, B frags from g_wout/g_wend.
// mode 0: h2 = relu(conv_out @ h1) -> fragments; mode 1: out = shift(conv_end @ h2)
// ---------------------------------------------------------------------------
__global__ void __launch_bounds__(512)
mm_kernel(float* __restrict__ outp, int mode) {
    int tid = threadIdx.x, lane = tid & 31, warp = tid >> 5, tt = warp & 7, oh = warp >> 3;
    int t0 = blockIdx.x * 128, obh = blockIdx.y, b = blockIdx.z;
    const unsigned* inF = (mode == 0) ? g_h1F : g_h2F;
    const unsigned* wF = (mode == 0) ? g_wout : g_wend;
    float D[8][4] = {};
    int tile0 = t0 >> 4;
    for (int ch = 0; ch < 4; ++ch) {
        const unsigned* Ah = inF + (size_t)b * 8 * FRAG64 + (size_t)ch * FRAG64 + tile0 * 1024;
        mma_AB<8>(D, Ah, Ah + 4 * FRAG64, wF + ch * 32768, 16384, tt, obh * 16 + oh * 8, lane);
    }
    int g = lane >> 2, tg = lane & 3, t1 = t0 + tt * 16 + g;
#pragma unroll
    for (int nt = 0; nt < 8; ++nt) {
        int o = obh * 128 + oh * 64 + nt * 8 + tg * 2;
        if (mode == 0) {
            int ch = o >> 6, kl = o & 63;
            unsigned* hb = g_h2F + (size_t)b * 8 * FRAG64 + (size_t)ch * FRAG64;
            unsigned* lb = hb + 4 * FRAG64;
            storeF(hb, lb, t1,     kl,     fmaxf(D[nt][0], 0.f));
            storeF(hb, lb, t1,     kl + 1, fmaxf(D[nt][1], 0.f));
            storeF(hb, lb, t1 + 8, kl,     fmaxf(D[nt][2], 0.f));
            storeF(hb, lb, t1 + 8, kl + 1, fmaxf(D[nt][3], 0.f));
        } else {
            size_t b0 = ((size_t)b * 256 + o) * TSEQ, b1 = b0 + TSEQ;
            int ta = t1 + 1, tb = t1 + 9;   // shift right by one
            if (ta < TSEQ) { outp[b0 + ta] = D[nt][0]; outp[b1 + ta] = D[nt][1]; }
            if (tb < TSEQ) { outp[b0 + tb] = D[nt][2]; outp[b1 + tb] = D[nt][3]; }
            if (t1 == 0) { outp[b0] = 0.f; outp[b1] = 0.f; }
        }
    }
}

// ---------------------------------------------------------------------------
extern "C" void kernel_launch(void* const* d_in, const int* in_sizes, int n_in,
                              void* d_out, int out_size) {
    const float* features   = (const float*)d_in[0];
    const int*   tokens     = (const int*)  d_in[1];
    const float* embed      = (const float*)d_in[2];
    const float* cond_W     = (const float*)d_in[3];
    const float* cond_b     = (const float*)d_in[4];
    const float* dilate_W   = (const float*)d_in[5];
    const float* dilate_b   = (const float*)d_in[6];
    const float* res_W      = (const float*)d_in[7];
    const float* res_b      = (const float*)d_in[8];
    const float* skip_W     = (const float*)d_in[9];
    const float* skip_b     = (const float*)d_in[10];
    const float* conv_out_W = (const float*)d_in[11];
    const float* conv_end_W = (const float*)d_in[12];

    float* outp      = (float*)d_out;                            // (B,256,T)
    float* ia_base   = outp + (size_t)TB * 256 * TSEQ;           // (B,L,128,T)
    float* cond_base = ia_base + (size_t)TB * NL * N2R * TSEQ;   // (B,L,128,T)

    static const int DILS[NL] = {1, 2, 4, 8, 16, 32, 64, 128, 256,
                                 1, 2, 4, 8, 16, 32, 64};

    cudaFuncSetAttribute(cond_kernel,  cudaFuncAttributeMaxDynamicSharedMemorySize, 66048);
    cudaFuncSetAttribute(layer_kernel, cudaFuncAttributeMaxDynamicSharedMemorySize, 66304);

    wprep<<<3824, 256>>>(dilate_W, res_W, skip_W, cond_W, conv_out_W, conv_end_W);
    embed_kernel<<<dim3(TSEQ / 256, TB), 256>>>(tokens, embed);
    cond_kernel<<<dim3(TSEQ / 128, 16, TB), 512, 66048>>>(features, cond_b, cond_base);

    for (int l = 0; l < NL; ++l)
        layer_kernel<<<dim3(TSEQ / 64, TB), 256, 66304>>>(
            dilate_b, res_b, cond_base, ia_base, l, DILS[l], l & 1);

    skip_kernel<<<dim3(TSEQ / 128, 2, TB), 512>>>(skip_b);
    mm_kernel<<<dim3(TSEQ / 128, 2, TB), 512>>>(nullptr, 0);
    mm_kernel<<<dim3(TSEQ / 128, 2, TB), 512>>>(outp, 1);
}